// round 3
// baseline (speedup 1.0000x reference)
#include <cuda_runtime.h>

#define IN 784
#define HIDN 64
#define KTOP 20
#define BMAX 131072

// Scratch (device globals — no allocation)
__device__ float g_WtE[IN * HIDN];        // [k][j] = W_enc[j][k]
__device__ float g_WtD[HIDN * IN];        // [j][i] = W_dec[i][j]
__device__ float g_hT[(size_t)HIDN * BMAX];  // gated h, transposed: [k][row]

// ---- f32x2 packed-FMA helpers ----
__device__ __forceinline__ unsigned long long pk_dup(float v) {
    unsigned long long r; unsigned u = __float_as_uint(v);
    asm("mov.b64 %0, {%1, %2};" : "=l"(r) : "r"(u), "r"(u));
    return r;
}
__device__ __forceinline__ void upk(unsigned long long v, float &lo, float &hi) {
    unsigned a, b;
    asm("mov.b64 {%0, %1}, %2;" : "=r"(a), "=r"(b) : "l"(v));
    lo = __uint_as_float(a); hi = __uint_as_float(b);
}
__device__ __forceinline__ void fma2(unsigned long long &acc, unsigned long long a, unsigned long long b) {
    asm("fma.rn.f32x2 %0, %1, %2, %0;" : "+l"(acc) : "l"(a), "l"(b));
}

// ---------------- K0: transpose weights ----------------
__global__ void k_prep(const float* __restrict__ We, const float* __restrict__ Wd) {
    int idx = blockIdx.x * 256 + threadIdx.x;
    if (idx < IN * HIDN) {
        int j = idx & (HIDN - 1), k = idx >> 6;
        g_WtE[idx] = We[j * IN + k];
        int i = idx % IN, jj = idx / IN;
        g_WtD[idx] = Wd[i * HIDN + jj];
    }
}

// ---------------- K1: encoder GEMM + bias + ReLU ----------------
// CTA 128 rows x 64 cols, 128 threads, thread tile 8 rows x 8 cols.
// K=784 in chunks of 16, double-buffered. Accumulators = row-pairs (f32x2).
__global__ __launch_bounds__(128) void k_enc(const float* __restrict__ x,
        const float* __restrict__ benc, float* __restrict__ hout, int B) {
    __shared__ float xs[2][16][132];   // transposed x chunk [k][row]
    __shared__ float ws[2][16][64];    // WtE chunk [k][j]
    const int tid = threadIdx.x;
    const int tx = tid & 7, ty = tid >> 3;     // 8 col-groups x 16 row-groups
    const int r0 = blockIdx.x * 128;
    const int c0 = tx * 8;

    // x loads: 4 float4 per thread per chunk. kq constant, rows (tid>>2)+32j.
    const int kq = tid & 3;
    const float* xp[4];
    #pragma unroll
    for (int j = 0; j < 4; j++) {
        int gr = r0 + (tid >> 2) + 32 * j; if (gr >= B) gr = B - 1;
        xp[j] = x + (size_t)gr * IN + kq * 4;
    }
    // ws loads: 2 float4 per thread per chunk. j4 constant, k (tid>>4)+8j.
    const int wj4 = tid & 15;
    const float* wp0 = g_WtE + ((tid >> 4) + 0) * HIDN + wj4 * 4;
    const float* wp1 = g_WtE + ((tid >> 4) + 8) * HIDN + wj4 * 4;

    unsigned long long acc[4][8];
    #pragma unroll
    for (int i = 0; i < 4; i++)
        #pragma unroll
        for (int j = 0; j < 8; j++) acc[i][j] = 0ull;

    // prologue: stage 0
    #pragma unroll
    for (int j = 0; j < 4; j++) {
        float4 v = *(const float4*)(xp[j]);
        int row = (tid >> 2) + 32 * j;
        xs[0][kq*4+0][row] = v.x; xs[0][kq*4+1][row] = v.y;
        xs[0][kq*4+2][row] = v.z; xs[0][kq*4+3][row] = v.w;
    }
    *(float4*)&ws[0][(tid >> 4) + 0][wj4*4] = *(const float4*)(wp0);
    *(float4*)&ws[0][(tid >> 4) + 8][wj4*4] = *(const float4*)(wp1);
    __syncthreads();

    for (int kb = 0; kb < IN; kb += 16) {
        const int cur = (kb >> 4) & 1;
        const bool more = (kb + 16) < IN;

        float4 px[4], pw0, pw1;
        if (more) {
            #pragma unroll
            for (int j = 0; j < 4; j++) px[j] = *(const float4*)(xp[j] + kb + 16);
            pw0 = *(const float4*)(wp0 + (kb + 16) * HIDN);
            pw1 = *(const float4*)(wp1 + (kb + 16) * HIDN);
        }

        #pragma unroll
        for (int k = 0; k < 16; k++) {
            const ulonglong2* ap = (const ulonglong2*)&xs[cur][k][ty * 8];
            ulonglong2 a01 = ap[0], a23 = ap[1];
            float4 bA = *(const float4*)&ws[cur][k][c0];
            float4 bB = *(const float4*)&ws[cur][k][c0 + 4];
            unsigned long long b0 = pk_dup(bA.x), b1 = pk_dup(bA.y),
                               b2 = pk_dup(bA.z), b3 = pk_dup(bA.w),
                               b4 = pk_dup(bB.x), b5 = pk_dup(bB.y),
                               b6 = pk_dup(bB.z), b7 = pk_dup(bB.w);
            #pragma unroll
            for (int rp = 0; rp < 4; rp++) {
                unsigned long long a = (rp == 0) ? a01.x : (rp == 1) ? a01.y
                                       : (rp == 2) ? a23.x : a23.y;
                fma2(acc[rp][0], a, b0); fma2(acc[rp][1], a, b1);
                fma2(acc[rp][2], a, b2); fma2(acc[rp][3], a, b3);
                fma2(acc[rp][4], a, b4); fma2(acc[rp][5], a, b5);
                fma2(acc[rp][6], a, b6); fma2(acc[rp][7], a, b7);
            }
        }

        if (more) {
            const int nxt = cur ^ 1;
            #pragma unroll
            for (int j = 0; j < 4; j++) {
                int row = (tid >> 2) + 32 * j;
                xs[nxt][kq*4+0][row] = px[j].x; xs[nxt][kq*4+1][row] = px[j].y;
                xs[nxt][kq*4+2][row] = px[j].z; xs[nxt][kq*4+3][row] = px[j].w;
            }
            *(float4*)&ws[nxt][(tid >> 4) + 0][wj4*4] = pw0;
            *(float4*)&ws[nxt][(tid >> 4) + 8][wj4*4] = pw1;
        }
        __syncthreads();
    }

    float4 beA = *(const float4*)(benc + c0);
    float4 beB = *(const float4*)(benc + c0 + 4);
    #pragma unroll
    for (int rp = 0; rp < 4; rp++) {
        float e[8], o[8];
        #pragma unroll
        for (int c = 0; c < 8; c++) upk(acc[rp][c], e[c], o[c]);
        int r = r0 + ty * 8 + rp * 2;
        if (r < B) {
            float4 u = make_float4(fmaxf(e[0]+beA.x,0.f), fmaxf(e[1]+beA.y,0.f),
                                   fmaxf(e[2]+beA.z,0.f), fmaxf(e[3]+beA.w,0.f));
            float4 v = make_float4(fmaxf(e[4]+beB.x,0.f), fmaxf(e[5]+beB.y,0.f),
                                   fmaxf(e[6]+beB.z,0.f), fmaxf(e[7]+beB.w,0.f));
            *(float4*)(hout + (size_t)r * HIDN + c0) = u;
            *(float4*)(hout + (size_t)r * HIDN + c0 + 4) = v;
        }
        if (r + 1 < B) {
            float4 u = make_float4(fmaxf(o[0]+beA.x,0.f), fmaxf(o[1]+beA.y,0.f),
                                   fmaxf(o[2]+beA.z,0.f), fmaxf(o[3]+beA.w,0.f));
            float4 v = make_float4(fmaxf(o[4]+beB.x,0.f), fmaxf(o[5]+beB.y,0.f),
                                   fmaxf(o[6]+beB.z,0.f), fmaxf(o[7]+beB.w,0.f));
            *(float4*)(hout + (size_t)(r+1) * HIDN + c0) = u;
            *(float4*)(hout + (size_t)(r+1) * HIDN + c0 + 4) = v;
        }
    }
}

// ---------------- K2: top-20 gating; writes gated h (row-major) + g_hT (transposed) ----------------
// 256 threads = 8 warps = 8 rows per block. Warp-per-row exact top-k
// (64-bit key: value bits << 32 | inverted index; post-ReLU so uint order == float order).
__global__ __launch_bounds__(256) void k_topk(float* __restrict__ h, int B) {
    __shared__ float sh[64][8];     // gated values [k][local row]
    int warp = threadIdx.x >> 5, lane = threadIdx.x & 31;
    int r0 = blockIdx.x * 8;
    int row = r0 + warp;
    if (row < B) {
        float* hr = h + (size_t)row * HIDN;
        float v0 = hr[lane], v1 = hr[lane + 32];
        unsigned long long k0 = ((unsigned long long)__float_as_uint(v0) << 32) | (unsigned)(63 - lane);
        unsigned long long k1 = ((unsigned long long)__float_as_uint(v1) << 32) | (unsigned)(31 - lane);
        float thr = 0.f;
        #pragma unroll
        for (int it = 0; it < KTOP; it++) {
            unsigned long long m = (k0 > k1) ? k0 : k1;
            #pragma unroll
            for (int off = 16; off > 0; off >>= 1) {
                unsigned long long o = __shfl_xor_sync(0xffffffffu, m, off);
                if (o > m) m = o;
            }
            if (it == KTOP - 1) thr = __uint_as_float((unsigned)(m >> 32));
            if (k0 == m) k0 = 0ull; else if (k1 == m) k1 = 0ull;
        }
        float g0 = (v0 >= thr) ? v0 : 0.f;
        float g1 = (v1 >= thr) ? v1 : 0.f;
        hr[lane]      = g0;
        hr[lane + 32] = g1;
        sh[lane][warp]      = g0;
        sh[lane + 32][warp] = g1;
    }
    __syncthreads();
    // coalesced transposed write: consecutive threads -> consecutive rows
    #pragma unroll
    for (int i = 0; i < 2; i++) {
        int k = (threadIdx.x >> 3) + i * 32;
        int r = threadIdx.x & 7;
        if (r0 + r < B) g_hT[(size_t)k * B + r0 + r] = sh[k][r];
    }
}

// ---------------- K3: decoder GEMM + bias ----------------
// CTA 128 rows x 64 cols, 128 threads, thread tile 8x8, K=64 (single tile).
// h tile loaded from g_hT (already transposed) -> coalesced, conflict-free.
__global__ __launch_bounds__(128) void k_dec(const float* __restrict__ bdec,
        float* __restrict__ xhat, int B) {
    __shared__ float hs[64][128];   // [k][row]
    __shared__ float ws[64][64];    // WtD[k][n0+..]
    const int tid = threadIdx.x;
    const int tx = tid & 7, ty = tid >> 3;
    const int r0 = blockIdx.x * 128;
    const int n0 = blockIdx.y * 64;
    const int c0 = tx * 8;

    // hs: 64 k x 128 rows = 2048 float4 / 128 thr = 16 per thread (coalesced)
    {
        int kk = tid >> 5, q = tid & 31;          // 4 k's per pass, 32 float4 each
        #pragma unroll
        for (int i = 0; i < 16; i++) {
            int k = kk + (i << 2);
            *(float4*)&hs[k][q * 4] = *(const float4*)(g_hT + (size_t)k * B + r0 + q * 4);
        }
    }
    // ws: 64x64 = 1024 float4 / 128 thr = 8 per thread (zero-pad cols >= IN)
    {
        int j4 = tid & 15;
        int col = n0 + j4 * 4;
        #pragma unroll
        for (int i = 0; i < 8; i++) {
            int k = (tid >> 4) + i * 8;
            float4 w = make_float4(0.f, 0.f, 0.f, 0.f);
            if (col < IN) w = *(const float4*)(g_WtD + (size_t)k * IN + col);
            *(float4*)&ws[k][j4 * 4] = w;
        }
    }
    __syncthreads();

    unsigned long long acc[4][8];
    #pragma unroll
    for (int i = 0; i < 4; i++)
        #pragma unroll
        for (int j = 0; j < 8; j++) acc[i][j] = 0ull;

    #pragma unroll 4
    for (int k = 0; k < 64; k++) {
        const ulonglong2* ap = (const ulonglong2*)&hs[k][ty * 8];
        ulonglong2 a01 = ap[0], a23 = ap[1];
        float4 bA = *(const float4*)&ws[k][c0];
        float4 bB = *(const float4*)&ws[k][c0 + 4];
        unsigned long long b0 = pk_dup(bA.x), b1 = pk_dup(bA.y),
                           b2 = pk_dup(bA.z), b3 = pk_dup(bA.w),
                           b4 = pk_dup(bB.x), b5 = pk_dup(bB.y),
                           b6 = pk_dup(bB.z), b7 = pk_dup(bB.w);
        #pragma unroll
        for (int rp = 0; rp < 4; rp++) {
            unsigned long long a = (rp == 0) ? a01.x : (rp == 1) ? a01.y
                                   : (rp == 2) ? a23.x : a23.y;
            fma2(acc[rp][0], a, b0); fma2(acc[rp][1], a, b1);
            fma2(acc[rp][2], a, b2); fma2(acc[rp][3], a, b3);
            fma2(acc[rp][4], a, b4); fma2(acc[rp][5], a, b5);
            fma2(acc[rp][6], a, b6); fma2(acc[rp][7], a, b7);
        }
    }

    int col = n0 + c0;
    if (col < IN) {   // 784 % 8 == 0 -> whole 8-col group valid or not
        float4 beA = *(const float4*)(bdec + col);
        float4 beB = *(const float4*)(bdec + col + 4);
        #pragma unroll
        for (int rp = 0; rp < 4; rp++) {
            float e[8], o[8];
            #pragma unroll
            for (int c = 0; c < 8; c++) upk(acc[rp][c], e[c], o[c]);
            int r = r0 + ty * 8 + rp * 2;
            if (r < B) {
                *(float4*)(xhat + (size_t)r * IN + col) =
                    make_float4(e[0]+beA.x, e[1]+beA.y, e[2]+beA.z, e[3]+beA.w);
                *(float4*)(xhat + (size_t)r * IN + col + 4) =
                    make_float4(e[4]+beB.x, e[5]+beB.y, e[6]+beB.z, e[7]+beB.w);
            }
            if (r + 1 < B) {
                *(float4*)(xhat + (size_t)(r+1) * IN + col) =
                    make_float4(o[0]+beA.x, o[1]+beA.y, o[2]+beA.z, o[3]+beA.w);
                *(float4*)(xhat + (size_t)(r+1) * IN + col + 4) =
                    make_float4(o[4]+beB.x, o[5]+beB.y, o[6]+beB.z, o[7]+beB.w);
            }
        }
    }
}

extern "C" void kernel_launch(void* const* d_in, const int* in_sizes, int n_in,
                              void* d_out, int out_size) {
    const float* x    = (const float*)d_in[0];
    const float* We   = (const float*)d_in[1];
    const float* benc = (const float*)d_in[2];
    const float* Wd   = (const float*)d_in[3];
    const float* bdec = (const float*)d_in[4];
    int B = in_sizes[0] / IN;

    float* hout = (float*)d_out;                         // [B, 64]
    float* xhat = (float*)d_out + (size_t)B * HIDN;      // [B, 784]

    k_prep<<<(IN * HIDN + 255) / 256, 256>>>(We, Wd);
    k_enc<<<(B + 127) / 128, 128>>>(x, benc, hout, B);
    k_topk<<<(B + 7) / 8, 256>>>(hout, B);
    k_dec<<<dim3((B + 127) / 128, (IN + 63) / 64), 128>>>(bdec, xhat, B);
}

// round 5
// speedup vs baseline: 1.0961x; 1.0961x over previous
#include <cuda_runtime.h>

#define IN 784
#define HIDN 64
#define KTOP 20
#define KCH_E 98              // 784/8 k-chunks (encoder)
#define KCH_D 8               // 64/8  k-chunks (decoder)
#define NPAD 832              // 13*64, padded decoder N
#define BMAX 131072
#define EPS_GAP 1e-4f

// Pre-split, pre-arranged weights (device globals — no allocation).
__device__ float g_Be[KCH_E * 2 * 8 * 64];     // [kc][hl][k][n] = split(W_enc[n][kc*8+k])
__device__ float g_Bd[KCH_D * 2 * 8 * NPAD];   // [kc][hl][k][n] = split(W_dec[n][kc*8+k])
__device__ int   g_nfix;
__device__ int   g_fixlist[BMAX];

// ---- tf32 helpers ----
__device__ __forceinline__ unsigned tf32r(float v) {
    unsigned r; asm("cvt.rna.tf32.f32 %0, %1;" : "=r"(r) : "f"(v)); return r;
}
__device__ __forceinline__ void split(float v, unsigned &hi, unsigned &lo) {
    hi = tf32r(v);
    lo = tf32r(v - __uint_as_float(hi));
}
__device__ __forceinline__ void mma8(float* c, const unsigned* a, unsigned b0, unsigned b1) {
    asm volatile(
        "mma.sync.aligned.m16n8k8.row.col.f32.tf32.tf32.f32 "
        "{%0,%1,%2,%3},{%4,%5,%6,%7},{%8,%9},{%0,%1,%2,%3};"
        : "+f"(c[0]), "+f"(c[1]), "+f"(c[2]), "+f"(c[3])
        : "r"(a[0]), "r"(a[1]), "r"(a[2]), "r"(a[3]), "r"(b0), "r"(b1));
}

// ---------------- K0: split + rearrange weights; zero fix counter ----------------
__global__ void k_prep(const float* __restrict__ We, const float* __restrict__ Wd) {
    int idx = blockIdx.x * 256 + threadIdx.x;
    if (idx == 0) g_nfix = 0;
    const int NE = KCH_E * 1024;
    if (idx < NE) {
        int kc = idx >> 10, r = idx & 1023;
        int hl = r >> 9, k = (r >> 6) & 7, n = r & 63;
        float w = We[n * IN + kc * 8 + k];
        unsigned h = tf32r(w);
        g_Be[idx] = hl ? __uint_as_float(tf32r(w - __uint_as_float(h)))
                       : __uint_as_float(h);
    }
    int j = idx - NE;
    const int ND = KCH_D * 2 * 8 * NPAD;
    if (j >= 0 && j < ND) {
        int kc = j / (2 * 8 * NPAD);
        int r  = j % (2 * 8 * NPAD);
        int hl = r / (8 * NPAD);
        int k  = (r / NPAD) & 7;
        int n  = r % NPAD;
        float w = (n < IN) ? Wd[n * HIDN + kc * 8 + k] : 0.f;
        unsigned h = tf32r(w);
        g_Bd[j] = hl ? __uint_as_float(tf32r(w - __uint_as_float(h)))
                     : __uint_as_float(h);
    }
}

// ---------------- K1: encoder GEMM (3xTF32) + bias + ReLU ----------------
__global__ __launch_bounds__(256) void k_enc(const float* __restrict__ x,
        const float* __restrict__ benc, float* __restrict__ hout, int B) {
    __shared__ float ws[2][2][8][68];
    const int tid = threadIdx.x, lane = tid & 31, w = tid >> 5;
    const int g = lane >> 2, tg = lane & 3;
    const int r0 = blockIdx.x * 128;
    const int row = r0 + w * 16 + g;
    const int rA = min(row, B - 1), rB = min(row + 8, B - 1);
    const float* xa = x + (size_t)rA * IN + 2 * tg;
    const float* xb = x + (size_t)rB * IN + 2 * tg;
    const int chl = tid >> 7, ck = (tid >> 4) & 7, cn4 = tid & 15;

    float acc[8][4];
    #pragma unroll
    for (int t = 0; t < 8; t++)
        #pragma unroll
        for (int i = 0; i < 4; i++) acc[t][i] = 0.f;

    {
        float4 v = *(const float4*)(g_Be + tid * 4);
        *(float4*)&ws[0][chl][ck][cn4 * 4] = v;
    }
    __syncthreads();

    for (int kc = 0; kc < KCH_E; kc++) {
        const int cur = kc & 1;
        const bool more = (kc + 1) < KCH_E;
        float4 pv;
        if (more) pv = *(const float4*)(g_Be + (kc + 1) * 1024 + tid * 4);

        float2 a01 = *(const float2*)(xa + kc * 8);
        float2 a23 = *(const float2*)(xb + kc * 8);
        unsigned ah[4], al[4];
        split(a01.x, ah[0], al[0]);
        split(a23.x, ah[1], al[1]);
        split(a01.y, ah[2], al[2]);
        split(a23.y, ah[3], al[3]);

        #pragma unroll
        for (int t = 0; t < 8; t++) {
            int n = t * 8 + g;
            unsigned bh0 = __float_as_uint(ws[cur][0][2*tg    ][n]);
            unsigned bh1 = __float_as_uint(ws[cur][0][2*tg + 1][n]);
            unsigned bl0 = __float_as_uint(ws[cur][1][2*tg    ][n]);
            unsigned bl1 = __float_as_uint(ws[cur][1][2*tg + 1][n]);
            mma8(acc[t], ah, bh0, bh1);
            mma8(acc[t], al, bh0, bh1);
            mma8(acc[t], ah, bl0, bl1);
        }

        if (more) *(float4*)&ws[cur ^ 1][chl][ck][cn4 * 4] = pv;
        __syncthreads();
    }

    #pragma unroll
    for (int t = 0; t < 8; t++) {
        int col = t * 8 + 2 * tg;
        float2 bb = *(const float2*)(benc + col);
        if (row < B) {
            float2 o = make_float2(fmaxf(acc[t][0] + bb.x, 0.f),
                                   fmaxf(acc[t][1] + bb.y, 0.f));
            *(float2*)(hout + (size_t)row * HIDN + col) = o;
        }
        if (row + 8 < B) {
            float2 o = make_float2(fmaxf(acc[t][2] + bb.x, 0.f),
                                   fmaxf(acc[t][3] + bb.y, 0.f));
            *(float2*)(hout + (size_t)(row + 8) * HIDN + col) = o;
        }
    }
}

// ---------------- K2: top-20 gating + fragile-row flagging ----------------
// Extract 21 maxima; if (v20 - v21) < EPS_GAP the tf32 selection may differ
// from fp32 -> append row to fix-list for exact recompute.
__global__ __launch_bounds__(256) void k_topk(float* __restrict__ h, int B) {
    int warp = threadIdx.x >> 5, lane = threadIdx.x & 31;
    int row = blockIdx.x * 8 + warp;
    if (row >= B) return;
    float* hr = h + (size_t)row * HIDN;
    float v0 = hr[lane], v1 = hr[lane + 32];
    unsigned long long k0 = ((unsigned long long)__float_as_uint(v0) << 32) | (unsigned)(63 - lane);
    unsigned long long k1 = ((unsigned long long)__float_as_uint(v1) << 32) | (unsigned)(31 - lane);
    float thr = 0.f, nxt = 0.f;
    #pragma unroll
    for (int it = 0; it < KTOP + 1; it++) {
        unsigned long long m = (k0 > k1) ? k0 : k1;
        #pragma unroll
        for (int off = 16; off > 0; off >>= 1) {
            unsigned long long o = __shfl_xor_sync(0xffffffffu, m, off);
            if (o > m) m = o;
        }
        if (it == KTOP - 1) thr = __uint_as_float((unsigned)(m >> 32));
        if (it == KTOP)     nxt = __uint_as_float((unsigned)(m >> 32));
        if (k0 == m) k0 = 0ull; else if (k1 == m) k1 = 0ull;
    }
    hr[lane]      = (v0 >= thr) ? v0 : 0.f;
    hr[lane + 32] = (v1 >= thr) ? v1 : 0.f;
    if (lane == 0 && (thr - nxt) < EPS_GAP) {
        int p = atomicAdd(&g_nfix, 1);
        if (p < BMAX) g_fixlist[p] = row;
    }
}

// ---------------- K2b: exact fp32 recompute of flagged rows ----------------
// Warp per flagged row: 64 dot products (2 cols/lane), bias+ReLU, top-20, write gated h.
__global__ __launch_bounds__(256) void k_fix(const float* __restrict__ x,
        const float* __restrict__ We, const float* __restrict__ benc,
        float* __restrict__ h, int B) {
    const int lane = threadIdx.x & 31;
    const int warpsTotal = (gridDim.x * blockDim.x) >> 5;
    const int wg = (blockIdx.x * blockDim.x + threadIdx.x) >> 5;
    int n = g_nfix; if (n > BMAX) n = BMAX;
    for (int i = wg; i < n; i += warpsTotal) {
        int row = g_fixlist[i];
        const float* xr = x + (size_t)row * IN;
        const float* wa = We + (size_t)lane * IN;
        const float* wb = We + (size_t)(lane + 32) * IN;
        float a0 = 0.f, a1 = 0.f;
        for (int k = 0; k < IN; k += 4) {
            float4 xv = *(const float4*)(xr + k);
            float4 va = *(const float4*)(wa + k);
            float4 vb = *(const float4*)(wb + k);
            a0 += xv.x*va.x + xv.y*va.y + xv.z*va.z + xv.w*va.w;
            a1 += xv.x*vb.x + xv.y*vb.y + xv.z*vb.z + xv.w*vb.w;
        }
        float v0 = fmaxf(a0 + benc[lane], 0.f);
        float v1 = fmaxf(a1 + benc[lane + 32], 0.f);
        unsigned long long k0 = ((unsigned long long)__float_as_uint(v0) << 32) | (unsigned)(63 - lane);
        unsigned long long k1 = ((unsigned long long)__float_as_uint(v1) << 32) | (unsigned)(31 - lane);
        float thr = 0.f;
        #pragma unroll
        for (int it = 0; it < KTOP; it++) {
            unsigned long long m = (k0 > k1) ? k0 : k1;
            #pragma unroll
            for (int off = 16; off > 0; off >>= 1) {
                unsigned long long o = __shfl_xor_sync(0xffffffffu, m, off);
                if (o > m) m = o;
            }
            if (it == KTOP - 1) thr = __uint_as_float((unsigned)(m >> 32));
            if (k0 == m) k0 = 0ull; else if (k1 == m) k1 = 0ull;
        }
        float* hr = h + (size_t)row * HIDN;
        hr[lane]      = (v0 >= thr) ? v0 : 0.f;
        hr[lane + 32] = (v1 >= thr) ? v1 : 0.f;
    }
}

// ---------------- K3: decoder GEMM (3xTF32) + bias ----------------
__global__ __launch_bounds__(256) void k_dec(const float* __restrict__ h,
        const float* __restrict__ bdec, float* __restrict__ xhat, int B) {
    __shared__ float ws[KCH_D][2][8][68];
    const int tid = threadIdx.x, lane = tid & 31, w = tid >> 5;
    const int g = lane >> 2, tg = lane & 3;
    const int r0 = blockIdx.x * 128;
    const int n0 = blockIdx.y * 64;
    const int row = r0 + w * 16 + g;
    const int rA = min(row, B - 1), rB = min(row + 8, B - 1);
    const float* ha = h + (size_t)rA * HIDN + 2 * tg;
    const float* hb = h + (size_t)rB * HIDN + 2 * tg;

    #pragma unroll
    for (int i = 0; i < 8; i++) {
        int f = tid + i * 256;
        int kc = f >> 8, hl = (f >> 7) & 1, k = (f >> 4) & 7, n4 = f & 15;
        float4 v = *(const float4*)(g_Bd + (size_t)(((kc * 2 + hl) * 8 + k)) * NPAD + n0 + n4 * 4);
        *(float4*)&ws[kc][hl][k][n4 * 4] = v;
    }
    __syncthreads();

    float acc[8][4];
    #pragma unroll
    for (int t = 0; t < 8; t++)
        #pragma unroll
        for (int i = 0; i < 4; i++) acc[t][i] = 0.f;

    #pragma unroll
    for (int kc = 0; kc < KCH_D; kc++) {
        float2 a01 = *(const float2*)(ha + kc * 8);
        float2 a23 = *(const float2*)(hb + kc * 8);
        unsigned ah[4], al[4];
        split(a01.x, ah[0], al[0]);
        split(a23.x, ah[1], al[1]);
        split(a01.y, ah[2], al[2]);
        split(a23.y, ah[3], al[3]);
        #pragma unroll
        for (int t = 0; t < 8; t++) {
            int n = t * 8 + g;
            unsigned bh0 = __float_as_uint(ws[kc][0][2*tg    ][n]);
            unsigned bh1 = __float_as_uint(ws[kc][0][2*tg + 1][n]);
            unsigned bl0 = __float_as_uint(ws[kc][1][2*tg    ][n]);
            unsigned bl1 = __float_as_uint(ws[kc][1][2*tg + 1][n]);
            mma8(acc[t], ah, bh0, bh1);
            mma8(acc[t], al, bh0, bh1);
            mma8(acc[t], ah, bl0, bl1);
        }
    }

    #pragma unroll
    for (int t = 0; t < 8; t++) {
        int col = n0 + t * 8 + 2 * tg;
        if (col < IN) {
            float2 bb = *(const float2*)(bdec + col);
            if (row < B) {
                float2 o = make_float2(acc[t][0] + bb.x, acc[t][1] + bb.y);
                *(float2*)(xhat + (size_t)row * IN + col) = o;
            }
            if (row + 8 < B) {
                float2 o = make_float2(acc[t][2] + bb.x, acc[t][3] + bb.y);
                *(float2*)(xhat + (size_t)(row + 8) * IN + col) = o;
            }
        }
    }
}

extern "C" void kernel_launch(void* const* d_in, const int* in_sizes, int n_in,
                              void* d_out, int out_size) {
    const float* x    = (const float*)d_in[0];
    const float* We   = (const float*)d_in[1];
    const float* benc = (const float*)d_in[2];
    const float* Wd   = (const float*)d_in[3];
    const float* bdec = (const float*)d_in[4];
    int B = in_sizes[0] / IN;

    float* hout = (float*)d_out;                         // [B, 64]
    float* xhat = (float*)d_out + (size_t)B * HIDN;      // [B, 784]

    const int NPREP = KCH_E * 1024 + KCH_D * 2 * 8 * NPAD;
    k_prep<<<(NPREP + 255) / 256, 256>>>(We, Wd);
    k_enc<<<(B + 127) / 128, 256>>>(x, benc, hout, B);
    k_topk<<<(B + 7) / 8, 256>>>(hout, B);
    k_fix<<<512, 256>>>(x, We, benc, hout, B);
    k_dec<<<dim3((B + 127) / 128, 13), 256>>>(hout, bdec, xhat, B);
}